// round 2
// baseline (speedup 1.0000x reference)
#include <cuda_runtime.h>
#include <math.h>

#define NQB 4
#define BB  512
#define SS  256
#define DD  64
#define HH  128
#define IN_DIM (HH + DD)   // 192

__device__ __forceinline__ float2 cmul(float2 a, float2 b) {
    return make_float2(a.x*b.x - a.y*b.y, a.x*b.y + a.y*b.x);
}

__device__ __forceinline__ float fast_sigmoid(float x) {
    return 1.0f / (1.0f + __expf(-x));
}
__device__ __forceinline__ float fast_tanh(float x) {
    // tanh(x) = 2*sigmoid(2x) - 1 ; saturates correctly at +-1 via expf->inf/0
    return 2.0f / (1.0f + __expf(-2.0f * x)) - 1.0f;
}

__global__ __launch_bounds__(128)
void qlstm_kernel(const float* __restrict__ x,
                  const float* __restrict__ W_in,
                  const float* __restrict__ b_in,
                  const float* __restrict__ W_out,
                  const float* __restrict__ b_out,
                  const float* __restrict__ w_f,
                  const float* __restrict__ w_i,
                  const float* __restrict__ w_u,
                  const float* __restrict__ w_o,
                  float* __restrict__ out,
                  int write_tails)
{
    __shared__ float  sWinT[NQB][IN_DIM];   // transposed W_in: [j][k]
    __shared__ float  sWout[NQB][HH];       // W_out row-major [j][h]
    __shared__ float  sBout[HH];
    __shared__ float  sBin[NQB];
    __shared__ float2 sUans[4][NQB][4];     // [gate][qubit][u00,u01,u10,u11]
    __shared__ float2 sUenc[NQB][4];        // per-step encoding matrices
    __shared__ float  sRed[4][NQB];         // y reduction scratch
    __shared__ float  sVqc[4][NQB];         // <Z_q> per gate

    const int tid  = threadIdx.x;
    const int lane = tid & 31;
    const int wid  = tid >> 5;          // warp = gate index: 0=f 1=i 2=u(g) 3=o
    const int b    = blockIdx.x;

    // ---- one-time setup: stage weights into SMEM ----
    for (int idx = tid; idx < IN_DIM * NQB; idx += 128) {
        int k = idx >> 2, j = idx & 3;          // W_in is (192,4) row-major
        sWinT[j][k] = W_in[idx];
    }
    for (int idx = tid; idx < NQB * HH; idx += 128)
        ((float*)sWout)[idx] = W_out[idx];      // (4,128) row-major already [j][h]
    sBout[tid] = b_out[tid & (HH - 1)];
    if (tid < NQB) sBin[tid] = b_in[tid];

    // Precompute fused ansatz matrices U = RZ(g)*RY(b)*RX(a) (constant weights)
    if (tid < 16) {
        int g = tid >> 2, q = tid & 3;
        const float* wg = (g == 0) ? w_f : (g == 1) ? w_i : (g == 2) ? w_u : w_o;
        float ha = wg[q]         * 0.5f;
        float hb = wg[NQB + q]   * 0.5f;
        float hg = wg[2*NQB + q] * 0.5f;
        float sa, ca, sb, cb, sg, cg;
        sincosf(ha, &sa, &ca);
        sincosf(hb, &sb, &cb);
        sincosf(hg, &sg, &cg);
        // M = RY*RX
        float2 m00 = make_float2( cb*ca,  sb*sa);
        float2 m01 = make_float2(-sb*ca, -cb*sa);
        float2 m10 = make_float2( sb*ca, -cb*sa);
        float2 m11 = make_float2( cb*ca, -sb*sa);
        float2 e0  = make_float2(cg, -sg);   // e^{-i g/2}
        float2 e1  = make_float2(cg,  sg);   // e^{+i g/2}
        sUans[g][q][0] = cmul(e0, m00);
        sUans[g][q][1] = cmul(e0, m01);
        sUans[g][q][2] = cmul(e1, m10);
        sUans[g][q][3] = cmul(e1, m11);
    }
    __syncthreads();

    float h_val = 0.0f, c_val = 0.0f;
    const float* xb = x + (size_t)b * SS * DD;
    float xv = (tid < DD) ? xb[tid] : 0.0f;     // prefetched x[b, t, tid]

    const int il = lane & 15;                    // amplitude index within 16-lane group

    for (int t = 0; t < SS; ++t) {
        // ---- 1. y = [h, x_t] @ W_in + b_in  (4 block reductions) ----
        float p0 = h_val * sWinT[0][tid];
        float p1 = h_val * sWinT[1][tid];
        float p2 = h_val * sWinT[2][tid];
        float p3 = h_val * sWinT[3][tid];
        if (tid < DD) {
            p0 += xv * sWinT[0][HH + tid];
            p1 += xv * sWinT[1][HH + tid];
            p2 += xv * sWinT[2][HH + tid];
            p3 += xv * sWinT[3][HH + tid];
        }
        // prefetch next step's x while reduction proceeds
        if (tid < DD && t + 1 < SS) xv = xb[(t + 1) * DD + tid];

        #pragma unroll
        for (int off = 16; off; off >>= 1) {
            p0 += __shfl_xor_sync(0xffffffffu, p0, off);
            p1 += __shfl_xor_sync(0xffffffffu, p1, off);
            p2 += __shfl_xor_sync(0xffffffffu, p2, off);
            p3 += __shfl_xor_sync(0xffffffffu, p3, off);
        }
        if (lane == 0) {
            sRed[wid][0] = p0; sRed[wid][1] = p1;
            sRed[wid][2] = p2; sRed[wid][3] = p3;
        }
        __syncthreads();

        // ---- fused encoding matrix U = RZ(atan(y^2)) * RY(atan(y)) * H ----
        if (tid < NQB) {
            float y  = sRed[0][tid] + sRed[1][tid] + sRed[2][tid] + sRed[3][tid] + sBin[tid];
            float ry = atanf(y)     * 0.5f;
            float rz = atanf(y * y) * 0.5f;
            float s, c, sp, cp;
            __sincosf(ry, &s, &c);
            __sincosf(rz, &sp, &cp);
            const float is2 = 0.70710678118654752440f;
            float A  = (c - s) * is2;
            float Bv = (c + s) * is2;
            sUenc[tid][0] = make_float2( cp*A,  -sp*A );   // e^{-i rz}(c-s)/sqrt2
            sUenc[tid][1] = make_float2( cp*Bv, -sp*Bv);   // e^{-i rz}(c+s)/sqrt2
            sUenc[tid][2] = make_float2( cp*Bv,  sp*Bv);   // e^{+i rz}(c+s)/sqrt2
            sUenc[tid][3] = make_float2(-cp*A,  -sp*A );   // e^{+i rz}(s-c)/sqrt2
        }
        __syncthreads();

        // ---- 2. VQC: warp `wid` simulates the 4-qubit circuit for its gate ----
        float2 amp = make_float2(il == 0 ? 1.0f : 0.0f, 0.0f);

        // encoding gates (fused H*RY*RZ per qubit)
        #pragma unroll
        for (int q = 0; q < NQB; ++q) {
            int m = 8 >> q;
            float2 oth;
            oth.x = __shfl_xor_sync(0xffffffffu, amp.x, m, 16);
            oth.y = __shfl_xor_sync(0xffffffffu, amp.y, m, 16);
            bool hi = (il & m) != 0;
            float2 a0 = hi ? oth : amp;
            float2 a1 = hi ? amp : oth;
            float2 v0 = sUenc[q][hi ? 2 : 0];
            float2 v1 = sUenc[q][hi ? 3 : 1];
            amp.x = v0.x*a0.x - v0.y*a0.y + v1.x*a1.x - v1.y*a1.y;
            amp.y = v0.x*a0.y + v0.y*a0.x + v1.x*a1.y + v1.y*a1.x;
        }
        // CNOT ring: (0,1)(1,2)(2,3)(3,0) — pure lane permutations
        #pragma unroll
        for (int q = 0; q < NQB; ++q) {
            int mc = 8 >> q;
            int mt = 8 >> ((q + 1) & 3);
            int src = il ^ ((il & mc) ? mt : 0);
            amp.x = __shfl_sync(0xffffffffu, amp.x, src, 16);
            amp.y = __shfl_sync(0xffffffffu, amp.y, src, 16);
        }
        // ansatz gates (fused RZ*RY*RX per qubit, constant matrices)
        #pragma unroll
        for (int q = 0; q < NQB; ++q) {
            int m = 8 >> q;
            float2 oth;
            oth.x = __shfl_xor_sync(0xffffffffu, amp.x, m, 16);
            oth.y = __shfl_xor_sync(0xffffffffu, amp.y, m, 16);
            bool hi = (il & m) != 0;
            float2 a0 = hi ? oth : amp;
            float2 a1 = hi ? amp : oth;
            float2 v0 = sUans[wid][q][hi ? 2 : 0];
            float2 v1 = sUans[wid][q][hi ? 3 : 1];
            amp.x = v0.x*a0.x - v0.y*a0.y + v1.x*a1.x - v1.y*a1.y;
            amp.y = v0.x*a0.y + v0.y*a0.x + v1.x*a1.y + v1.y*a1.x;
        }

        // <Z_q> = sum over amplitudes of (+/-)|amp|^2
        float p  = amp.x*amp.x + amp.y*amp.y;
        float z0 = (il & 8) ? -p : p;
        float z1 = (il & 4) ? -p : p;
        float z2 = (il & 2) ? -p : p;
        float z3 = (il & 1) ? -p : p;
        #pragma unroll
        for (int off = 8; off; off >>= 1) {
            z0 += __shfl_xor_sync(0xffffffffu, z0, off, 16);
            z1 += __shfl_xor_sync(0xffffffffu, z1, off, 16);
            z2 += __shfl_xor_sync(0xffffffffu, z2, off, 16);
            z3 += __shfl_xor_sync(0xffffffffu, z3, off, 16);
        }
        if (lane == 0) {
            sVqc[wid][0] = z0; sVqc[wid][1] = z1;
            sVqc[wid][2] = z2; sVqc[wid][3] = z3;
        }
        __syncthreads();

        // ---- 3. gate projections + LSTM cell (one hidden dim per thread) ----
        float bo = sBout[tid];
        float af = bo, ai = bo, ag = bo, ao = bo;
        #pragma unroll
        for (int j = 0; j < NQB; ++j) {
            float wj = sWout[j][tid];
            af += sVqc[0][j] * wj;
            ai += sVqc[1][j] * wj;
            ag += sVqc[2][j] * wj;
            ao += sVqc[3][j] * wj;
        }
        float f = fast_sigmoid(af);
        float i = fast_sigmoid(ai);
        float g = fast_tanh(ag);
        float o = fast_sigmoid(ao);
        c_val = f * c_val + i * g;
        h_val = o * fast_tanh(c_val);

        out[(size_t)b * SS * HH + (size_t)t * HH + tid] = h_val;
    }

    if (write_tails) {
        size_t base = (size_t)BB * SS * HH;
        out[base + (size_t)b * HH + tid] = h_val;                         // hT
        out[base + (size_t)BB * HH + (size_t)b * HH + tid] = c_val;       // cT
    }
}

extern "C" void kernel_launch(void* const* d_in, const int* in_sizes, int n_in,
                              void* d_out, int out_size) {
    const float* x     = (const float*)d_in[0];
    const float* W_in  = (const float*)d_in[1];
    const float* b_in  = (const float*)d_in[2];
    const float* W_out = (const float*)d_in[3];
    const float* b_out = (const float*)d_in[4];
    const float* w_f   = (const float*)d_in[5];
    const float* w_i   = (const float*)d_in[6];
    const float* w_u   = (const float*)d_in[7];
    const float* w_o   = (const float*)d_in[8];
    float* out = (float*)d_out;

    int need_tail = (size_t)out_size >= (size_t)BB * SS * HH + 2 * (size_t)BB * HH;
    qlstm_kernel<<<BB, HH>>>(x, W_in, b_in, W_out, b_out,
                             w_f, w_i, w_u, w_o, out, need_tail);
}